// round 2
// baseline (speedup 1.0000x reference)
#include <cuda_runtime.h>
#include <cuda_bf16.h>
#include <cstdint>

// ============ sm_103-safe primitives (NO tcgen05 / 'a'-features) ============
__device__ __forceinline__ uint32_t smem_u32(const void* p) {
    uint32_t a;
    asm("{ .reg .u64 t; cvta.to.shared.u64 t, %1; cvt.u32.u64 %0, t; }" : "=r"(a) : "l"(p));
    return a;
}
__device__ __forceinline__ void ldsm4(uint32_t r[4], uint32_t addr) {
    asm volatile("ldmatrix.sync.aligned.m8n8.x4.shared.b16 {%0,%1,%2,%3}, [%4];"
                 : "=r"(r[0]), "=r"(r[1]), "=r"(r[2]), "=r"(r[3]) : "r"(addr));
}
__device__ __forceinline__ void ldsm4t(uint32_t r[4], uint32_t addr) {
    asm volatile("ldmatrix.sync.aligned.m8n8.x4.trans.shared.b16 {%0,%1,%2,%3}, [%4];"
                 : "=r"(r[0]), "=r"(r[1]), "=r"(r[2]), "=r"(r[3]) : "r"(addr));
}
__device__ __forceinline__ void mma16816(float c[4], const uint32_t a[4],
                                         uint32_t b0, uint32_t b1) {
    asm volatile(
        "mma.sync.aligned.m16n8k16.row.col.f32.bf16.bf16.f32 "
        "{%0,%1,%2,%3},{%4,%5,%6,%7},{%8,%9},{%0,%1,%2,%3};"
        : "+f"(c[0]), "+f"(c[1]), "+f"(c[2]), "+f"(c[3])
        : "r"(a[0]), "r"(a[1]), "r"(a[2]), "r"(a[3]), "r"(b0), "r"(b1));
}
__device__ __forceinline__ uint32_t pack2(__nv_bfloat16 lo, __nv_bfloat16 hi) {
    return ((uint32_t)__bfloat16_as_ushort(hi) << 16) | (uint32_t)__bfloat16_as_ushort(lo);
}
#define SWZ128(o) ((o) ^ (((o) >> 3) & 0x70))
#define SWZ256(o) ((o) ^ (((o) >> 4) & 0x70))

// ============ problem constants ============
#define FIN  1024
#define SEQ  128
#define KC   64
#define NKC  16

// ============ SMEM layout (bytes) ============
#define WT_H   0            // W chunk hi : 128 x 64 bf16, 128B rows
#define WT_L   16384
#define XT_H   32768        // x chunk hi : 64 x 128 bf16, 256B rows
#define XT_L   49152
#define QT_H   65536        // qT hi : 2 heads x [128 s][64 d] bf16
#define QT_L   98304
#define KT_H   131072
#define KT_L   163840
#define W_SM   196608       // 2 x 128 floats
#define BQ_SM  197632
#define BK_SM  198144
#define WO_SM  198656
#define SMEM_TOTAL 199168

__global__ void __launch_bounds__(256, 1)
Attention_75402445849133_kernel(const float* __restrict__ x,
                                const float* __restrict__ Wq, const float* __restrict__ bq,
                                const float* __restrict__ Wk, const float* __restrict__ bk,
                                const float* __restrict__ Wo, const float* __restrict__ bo,
                                float* __restrict__ out)
{
    extern __shared__ char smem[];
    const uint32_t sbase = smem_u32(smem);
    const int tid = threadIdx.x;
    const int w   = tid >> 5;
    const int lid = tid & 31;
    const int gq  = lid >> 2;     // mma "group" (row id)
    const int tq  = lid & 3;      // mma "quad"  (col id)
    const int g   = blockIdx.x;   // channel group (2 heads)
    const int b   = blockIdx.y;

    float* wsm = (float*)(smem + W_SM);
    float* bqs = (float*)(smem + BQ_SM);
    float* bks = (float*)(smem + BK_SM);
    float* wos = (float*)(smem + WO_SM);
    if (tid < 128) {
        bqs[tid] = bq[g * 128 + tid];
        bks[tid] = bk[g * 128 + tid];
        wos[tid] = Wo[tid];
    }
    wsm[tid] = 0.0f;

    const float* xb = x + (size_t)b * FIN * SEQ;
    const int m0  = (w & 3) * 32;   // warp's channel-row tile
    const int n0w = (w >> 2) * 64;  // warp's s-column tile

    // ================= Phase 1: projections (p=0 -> Q, p=1 -> K) =================
    #pragma unroll 1
    for (int p = 0; p < 2; p++) {
        const float* Wg = (p ? Wk : Wq) + (size_t)g * 128 * FIN;
        float creg[2][8][4];
        #pragma unroll
        for (int a = 0; a < 2; a++)
            #pragma unroll
            for (int bnt = 0; bnt < 8; bnt++)
                #pragma unroll
                for (int j = 0; j < 4; j++) creg[a][bnt][j] = 0.0f;

        #pragma unroll 1
        for (int kc = 0; kc < NKC; kc++) {
            __syncthreads();
            // ---- load W chunk (128 x 64 fp32) -> split bf16, swizzled 128B rows
            const float* Wc = Wg + kc * KC;
            #pragma unroll
            for (int i = 0; i < 16; i++) {
                int p2 = i * 256 + tid;
                int row = p2 >> 5, kp = p2 & 31;
                float2 wv = *(const float2*)(Wc + (size_t)row * FIN + kp * 2);
                __nv_bfloat16 h0 = __float2bfloat16(wv.x);
                __nv_bfloat16 h1 = __float2bfloat16(wv.y);
                __nv_bfloat16 l0 = __float2bfloat16(wv.x - __bfloat162float(h0));
                __nv_bfloat16 l1 = __float2bfloat16(wv.y - __bfloat162float(h1));
                uint32_t off = SWZ128((uint32_t)(row * 128 + kp * 4));
                *(uint32_t*)(smem + WT_H + off) = pack2(h0, h1);
                *(uint32_t*)(smem + WT_L + off) = pack2(l0, l1);
            }
            // ---- load x chunk (64 x 128 fp32) -> split bf16, swizzled 256B rows
            #pragma unroll
            for (int i = 0; i < 8; i++) {
                int q2 = i * 256 + tid;
                int kr = q2 >> 5, sq = q2 & 31;
                float4 xv = *(const float4*)(xb + (size_t)(kc * KC + kr) * SEQ + sq * 4);
                __nv_bfloat16 h0 = __float2bfloat16(xv.x), h1 = __float2bfloat16(xv.y);
                __nv_bfloat16 h2 = __float2bfloat16(xv.z), h3 = __float2bfloat16(xv.w);
                __nv_bfloat16 l0 = __float2bfloat16(xv.x - __bfloat162float(h0));
                __nv_bfloat16 l1 = __float2bfloat16(xv.y - __bfloat162float(h1));
                __nv_bfloat16 l2 = __float2bfloat16(xv.z - __bfloat162float(h2));
                __nv_bfloat16 l3 = __float2bfloat16(xv.w - __bfloat162float(h3));
                uint32_t off = SWZ256((uint32_t)(kr * 256 + sq * 8));
                *(uint2*)(smem + XT_H + off) = make_uint2(pack2(h0, h1), pack2(h2, h3));
                *(uint2*)(smem + XT_L + off) = make_uint2(pack2(l0, l1), pack2(l2, l3));
            }
            __syncthreads();

            // ---- MMA: C(128ch x 128s) += W * x, 3-way bf16 split
            #pragma unroll
            for (int ks = 0; ks < 4; ks++) {
                const int k0 = ks * 16;
                uint32_t aH[2][4], aL[2][4];
                #pragma unroll
                for (int mt = 0; mt < 2; mt++) {
                    int row = m0 + mt * 16 + (lid & 15);
                    int col = k0 + ((lid >> 4) << 3);
                    uint32_t off = SWZ128((uint32_t)(row * 128 + col * 2));
                    ldsm4(aH[mt], sbase + WT_H + off);
                    ldsm4(aL[mt], sbase + WT_L + off);
                }
                uint32_t bH[4][4], bL[4][4];
                #pragma unroll
                for (int np = 0; np < 4; np++) {
                    int tL  = lid >> 3;
                    int krw = k0 + ((tL & 1) << 3) + (lid & 7);
                    int nc  = n0w + np * 16 + ((tL >> 1) << 3);
                    uint32_t off = SWZ256((uint32_t)(krw * 256 + nc * 2));
                    ldsm4t(bH[np], sbase + XT_H + off);
                    ldsm4t(bL[np], sbase + XT_L + off);
                }
                #pragma unroll
                for (int mt = 0; mt < 2; mt++)
                    #pragma unroll
                    for (int nt = 0; nt < 8; nt++) {
                        const uint32_t* bh = &bH[nt >> 1][(nt & 1) * 2];
                        const uint32_t* bl = &bL[nt >> 1][(nt & 1) * 2];
                        mma16816(creg[mt][nt], aH[mt], bh[0], bh[1]);
                        mma16816(creg[mt][nt], aH[mt], bl[0], bl[1]);
                        mma16816(creg[mt][nt], aL[mt], bh[0], bh[1]);
                    }
            }
        }
        // ---- writeback: C[ch][s] -> (q|k)T[head][s][d] split bf16 (+bias, q*0.125)
        {
            const int dstH = p ? KT_H : QT_H;
            const int dstL = p ? KT_L : QT_L;
            #pragma unroll
            for (int mt = 0; mt < 2; mt++)
                #pragma unroll
                for (int rj = 0; rj < 2; rj++) {
                    int m = m0 + mt * 16 + rj * 8 + gq;
                    float bias = p ? bks[m] : bqs[m];
                    int head = m >> 6, d = m & 63;
                    char* dh = smem + dstH + head * 16384;
                    char* dl = smem + dstL + head * 16384;
                    #pragma unroll
                    for (int nt = 0; nt < 8; nt++)
                        #pragma unroll
                        for (int jj = 0; jj < 2; jj++) {
                            int n = n0w + nt * 8 + tq * 2 + jj;
                            float v = creg[mt][nt][rj * 2 + jj] + bias;
                            if (!p) v *= 0.125f;
                            __nv_bfloat16 h = __float2bfloat16(v);
                            __nv_bfloat16 l = __float2bfloat16(v - __bfloat162float(h));
                            uint32_t off = SWZ128((uint32_t)(n * 128 + d * 2));
                            *(__nv_bfloat16*)(dh + off) = h;
                            *(__nv_bfloat16*)(dl + off) = l;
                        }
                }
        }
    }
    __syncthreads();

    // ================= Phase 2: scores + softmax + w reduction =================
    {
        const int head = w >> 2;
        const int sb0  = (w & 3) * 32;
        const uint32_t qh = sbase + QT_H + head * 16384;
        const uint32_t ql = sbase + QT_L + head * 16384;
        const uint32_t kh = sbase + KT_H + head * 16384;
        const uint32_t kl = sbase + KT_L + head * 16384;

        float wacc[16][2];
        #pragma unroll
        for (int nt = 0; nt < 16; nt++) { wacc[nt][0] = 0.f; wacc[nt][1] = 0.f; }

        #pragma unroll 1
        for (int chunk = 0; chunk < 2; chunk++) {
            const int s0 = sb0 + chunk * 16;
            float sc[16][4];
            #pragma unroll
            for (int nt = 0; nt < 16; nt++)
                #pragma unroll
                for (int j = 0; j < 4; j++) sc[nt][j] = 0.f;

            #pragma unroll
            for (int ks = 0; ks < 4; ks++) {
                const int k0 = ks * 16;
                uint32_t aH[4], aL[4];
                {
                    int row = s0 + (lid & 15);
                    int col = k0 + ((lid >> 4) << 3);
                    uint32_t off = SWZ128((uint32_t)(row * 128 + col * 2));
                    ldsm4(aH, qh + off);
                    ldsm4(aL, ql + off);
                }
                #pragma unroll
                for (int np = 0; np < 8; np++) {
                    int tL   = lid >> 3;
                    int rrow = np * 16 + ((tL >> 1) << 3) + (lid & 7);
                    int ccol = k0 + ((tL & 1) << 3);
                    uint32_t off = SWZ128((uint32_t)(rrow * 128 + ccol * 2));
                    uint32_t bH[4], bLr[4];
                    ldsm4(bH, kh + off);
                    ldsm4(bLr, kl + off);
                    mma16816(sc[np * 2],     aH, bH[0],  bH[1]);
                    mma16816(sc[np * 2],     aH, bLr[0], bLr[1]);
                    mma16816(sc[np * 2],     aL, bH[0],  bH[1]);
                    mma16816(sc[np * 2 + 1], aH, bH[2],  bH[3]);
                    mma16816(sc[np * 2 + 1], aH, bLr[2], bLr[3]);
                    mma16816(sc[np * 2 + 1], aL, bH[2],  bH[3]);
                }
            }
            // softmax over t (128 cols fully in-warp per row)
            float mx0 = -1e30f, mx1 = -1e30f;
            #pragma unroll
            for (int nt = 0; nt < 16; nt++) {
                mx0 = fmaxf(mx0, fmaxf(sc[nt][0], sc[nt][1]));
                mx1 = fmaxf(mx1, fmaxf(sc[nt][2], sc[nt][3]));
            }
            mx0 = fmaxf(mx0, __shfl_xor_sync(0xffffffffu, mx0, 1));
            mx0 = fmaxf(mx0, __shfl_xor_sync(0xffffffffu, mx0, 2));
            mx1 = fmaxf(mx1, __shfl_xor_sync(0xffffffffu, mx1, 1));
            mx1 = fmaxf(mx1, __shfl_xor_sync(0xffffffffu, mx1, 2));
            float Z0 = 0.f, Z1 = 0.f;
            #pragma unroll
            for (int nt = 0; nt < 16; nt++) {
                sc[nt][0] = __expf(sc[nt][0] - mx0); Z0 += sc[nt][0];
                sc[nt][1] = __expf(sc[nt][1] - mx0); Z0 += sc[nt][1];
                sc[nt][2] = __expf(sc[nt][2] - mx1); Z1 += sc[nt][2];
                sc[nt][3] = __expf(sc[nt][3] - mx1); Z1 += sc[nt][3];
            }
            Z0 += __shfl_xor_sync(0xffffffffu, Z0, 1);
            Z0 += __shfl_xor_sync(0xffffffffu, Z0, 2);
            Z1 += __shfl_xor_sync(0xffffffffu, Z1, 1);
            Z1 += __shfl_xor_sync(0xffffffffu, Z1, 2);
            const float c0 = wos[s0 + gq]     / Z0;
            const float c1 = wos[s0 + 8 + gq] / Z1;
            #pragma unroll
            for (int nt = 0; nt < 16; nt++) {
                wacc[nt][0] += sc[nt][0] * c0 + sc[nt][2] * c1;
                wacc[nt][1] += sc[nt][1] * c0 + sc[nt][3] * c1;
            }
        }
        // reduce over row-groups (g) with butterfly, then 4 lanes commit
        #pragma unroll
        for (int d = 4; d < 32; d <<= 1)
            #pragma unroll
            for (int nt = 0; nt < 16; nt++) {
                wacc[nt][0] += __shfl_xor_sync(0xffffffffu, wacc[nt][0], d);
                wacc[nt][1] += __shfl_xor_sync(0xffffffffu, wacc[nt][1], d);
            }
        if (lid < 4) {
            #pragma unroll
            for (int nt = 0; nt < 16; nt++) {
                atomicAdd(&wsm[head * 128 + nt * 8 + 2 * lid],     wacc[nt][0]);
                atomicAdd(&wsm[head * 128 + nt * 8 + 2 * lid + 1], wacc[nt][1]);
            }
        }
    }
    __syncthreads();

    // ================= Phase 3: out[b, g*128+f] = sum_t w[head][t] * x[b,f,t] + bo
    if (tid < 128) {
        const float* wv = wsm + (tid >> 6) * 128;
        const float4* x4 = (const float4*)(xb + (size_t)(g * 128 + tid) * SEQ);
        float acc = 0.f;
        #pragma unroll 8
        for (int t4 = 0; t4 < 32; t4++) {
            float4 xv = x4[t4];
            acc += xv.x * wv[t4 * 4 + 0] + xv.y * wv[t4 * 4 + 1]
                 + xv.z * wv[t4 * 4 + 2] + xv.w * wv[t4 * 4 + 3];
        }
        out[(size_t)b * FIN + g * 128 + tid] = acc + bo[0];
    }
}

extern "C" void kernel_launch(void* const* d_in, const int* in_sizes, int n_in,
                              void* d_out, int out_size)
{
    (void)in_sizes; (void)n_in; (void)out_size;
    const float* x  = (const float*)d_in[0];
    const float* Wq = (const float*)d_in[1];
    const float* bq = (const float*)d_in[2];
    const float* Wk = (const float*)d_in[3];
    const float* bk = (const float*)d_in[4];
    const float* Wo = (const float*)d_in[5];
    const float* bo = (const float*)d_in[6];
    float* out = (float*)d_out;

    cudaFuncSetAttribute(Attention_75402445849133_kernel,
                         cudaFuncAttributeMaxDynamicSharedMemorySize, SMEM_TOTAL);
    dim3 grid(8, 256, 1);
    Attention_75402445849133_kernel<<<grid, 256, SMEM_TOTAL>>>(x, Wq, bq, Wk, bk, Wo, bo, out);
}